// round 2
// baseline (speedup 1.0000x reference)
#include <cuda_runtime.h>

#define L_SEQ 2048
#define BATCH 16
#define NDIM  512
#define HDIM  512
#define NCH   128
#define CLEN  16

typedef unsigned long long u64;

__device__ float g_tA [NDIM * NDIM];
__device__ float g_tBm[HDIM * NDIM];
__device__ float g_pw [7 * NDIM * NDIM];
__device__ float g_t0 [NDIM * NDIM];
__device__ float g_t1 [NDIM * NDIM];
__device__ float g_Bx [(size_t)L_SEQ * NDIM * BATCH];
__device__ float g_E  [2 * NCH * NDIM * BATCH];

__device__ __forceinline__ u64 pk2(float x) {
    u64 r; asm("mov.b64 %0, {%1, %1};" : "=l"(r) : "f"(x)); return r;
}
__device__ __forceinline__ void fma2(u64 &d, u64 a, u64 b) {
    asm("fma.rn.f32x2 %0, %1, %2, %3;" : "=l"(d) : "l"(a), "l"(b), "l"(d));
}
__device__ __forceinline__ float2 upk(u64 v) {
    float2 f; asm("mov.b64 {%0, %1}, %2;" : "=f"(f.x), "=f"(f.y) : "l"(v)); return f;
}

// acc[b 0..3][npair 0..3] += sum_k tM[k][n0..n0+7] * hs[k][b0..b0+3]
__device__ __forceinline__ void gemm_step(
    const float* __restrict__ tM, const float* __restrict__ hs,
    float* __restrict__ As, u64 acc[4][4], int tid, int n0, int b0)
{
#pragma unroll
    for (int j = 0; j < 4; j++)
#pragma unroll
        for (int ip = 0; ip < 4; ip++) acc[j][ip] = 0ull;

#pragma unroll 1
    for (int kt = 0; kt < NDIM / 32; kt++) {
        const float4* src = (const float4*)(tM + (size_t)kt * 32 * NDIM);
        float4* dst = (float4*)As;
#pragma unroll
        for (int i = 0; i < 16; i++) dst[tid + 256 * i] = src[tid + 256 * i];
        __syncthreads();
#pragma unroll
        for (int kk = 0; kk < 32; kk++) {
            const int k = kt * 32 + kk;
            ulonglong2 a01 = *(const ulonglong2*)(As + kk * NDIM + n0);
            ulonglong2 a23 = *(const ulonglong2*)(As + kk * NDIM + n0 + 4);
            float4 hb = *(const float4*)(hs + k * BATCH + b0);
            u64 hp;
            hp = pk2(hb.x);
            fma2(acc[0][0], a01.x, hp); fma2(acc[0][1], a01.y, hp);
            fma2(acc[0][2], a23.x, hp); fma2(acc[0][3], a23.y, hp);
            hp = pk2(hb.y);
            fma2(acc[1][0], a01.x, hp); fma2(acc[1][1], a01.y, hp);
            fma2(acc[1][2], a23.x, hp); fma2(acc[1][3], a23.y, hp);
            hp = pk2(hb.z);
            fma2(acc[2][0], a01.x, hp); fma2(acc[2][1], a01.y, hp);
            fma2(acc[2][2], a23.x, hp); fma2(acc[2][3], a23.y, hp);
            hp = pk2(hb.w);
            fma2(acc[3][0], a01.x, hp); fma2(acc[3][1], a01.y, hp);
            fma2(acc[3][2], a23.x, hp); fma2(acc[3][3], a23.y, hp);
        }
        __syncthreads();
    }
}

__device__ __forceinline__ void store_nb(float* dst, float2 v[4][4], int n0, int b0) {
#pragma unroll
    for (int r = 0; r < 8; r++) {
        int ip = r >> 1;
        float4 w = (r & 1) == 0
            ? make_float4(v[0][ip].x, v[1][ip].x, v[2][ip].x, v[3][ip].x)
            : make_float4(v[0][ip].y, v[1][ip].y, v[2][ip].y, v[3][ip].y);
        *(float4*)(dst + (n0 + r) * BATCH + b0) = w;
    }
}

__device__ __forceinline__ void add_nb(const float* src, float2 v[4][4], int n0, int b0) {
#pragma unroll
    for (int r = 0; r < 8; r++) {
        float4 q = *(const float4*)(src + (n0 + r) * BATCH + b0);
        int ip = r >> 1;
        if ((r & 1) == 0) {
            v[0][ip].x += q.x; v[1][ip].x += q.y; v[2][ip].x += q.z; v[3][ip].x += q.w;
        } else {
            v[0][ip].y += q.x; v[1][ip].y += q.y; v[2][ip].y += q.z; v[3][ip].y += q.w;
        }
    }
}

__global__ void k_tr(const float* __restrict__ src, float* __restrict__ dst)
{
    __shared__ float tile[32][33];
    int x = blockIdx.x * 32 + threadIdx.x;
    int y = blockIdx.y * 32 + threadIdx.y;
#pragma unroll
    for (int r = 0; r < 32; r += 8)
        tile[threadIdx.y + r][threadIdx.x] = src[(size_t)(y + r) * NDIM + x];
    __syncthreads();
    x = blockIdx.y * 32 + threadIdx.x;
    y = blockIdx.x * 32 + threadIdx.y;
#pragma unroll
    for (int r = 0; r < 32; r += 8)
        dst[(size_t)(y + r) * NDIM + x] = tile[threadIdx.x][threadIdx.y + r];
}

// S = P @ P, row-major 512x512
__global__ __launch_bounds__(256) void k_sq(
    const float* __restrict__ P, float* __restrict__ S)
{
    __shared__ float Ta[16][68];
    __shared__ float Tb[16][64];
    const int tid = threadIdx.x;
    const int ib = blockIdx.y * 64, jb = blockIdx.x * 64;
    const int i0 = (tid >> 4) * 4, j0 = (tid & 15) * 4;
    u64 acc[4][2];
#pragma unroll
    for (int i = 0; i < 4; i++) { acc[i][0] = 0ull; acc[i][1] = 0ull; }

#pragma unroll 1
    for (int kt = 0; kt < 32; kt++) {
        const int k0 = kt * 16;
        {
            int i = tid >> 2, k4 = (tid & 3) * 4;
            float4 q = *(const float4*)(P + (size_t)(ib + i) * NDIM + k0 + k4);
            Ta[k4 + 0][i] = q.x; Ta[k4 + 1][i] = q.y;
            Ta[k4 + 2][i] = q.z; Ta[k4 + 3][i] = q.w;
        }
        {
            int kk = tid >> 4, j4 = (tid & 15) * 4;
            *(float4*)&Tb[kk][j4] = *(const float4*)(P + (size_t)(k0 + kk) * NDIM + jb + j4);
        }
        __syncthreads();
#pragma unroll
        for (int k = 0; k < 16; k++) {
            float4 av = *(const float4*)&Ta[k][i0];
            ulonglong2 bv = *(const ulonglong2*)&Tb[k][j0];
            u64 ap;
            ap = pk2(av.x); fma2(acc[0][0], bv.x, ap); fma2(acc[0][1], bv.y, ap);
            ap = pk2(av.y); fma2(acc[1][0], bv.x, ap); fma2(acc[1][1], bv.y, ap);
            ap = pk2(av.z); fma2(acc[2][0], bv.x, ap); fma2(acc[2][1], bv.y, ap);
            ap = pk2(av.w); fma2(acc[3][0], bv.x, ap); fma2(acc[3][1], bv.y, ap);
        }
        __syncthreads();
    }
#pragma unroll
    for (int i = 0; i < 4; i++) {
        float2 p0 = upk(acc[i][0]), p1 = upk(acc[i][1]);
        float4 w = make_float4(p0.x, p0.y, p1.x, p1.y);
        *(float4*)(S + (size_t)(ib + i0 + i) * NDIM + jb + j0) = w;
    }
}

extern __shared__ float smem[];

__global__ __launch_bounds__(256) void k_bx(const float* __restrict__ inputs)
{
    float* As = smem;
    float* xs = smem + 32 * NDIM;
    const int tid = threadIdx.x;
    const int t = blockIdx.x;
    const int b0 = (tid & 3) * 4, n0 = (tid >> 2) * 8;

    for (int i = tid; i < HDIM * BATCH; i += 256) {
        int b = i >> 9, h = i & (HDIM - 1);
        xs[h * BATCH + b] = inputs[(size_t)b * (L_SEQ * HDIM) + (size_t)t * HDIM + h];
    }
    __syncthreads();

    u64 acc[4][4];
    gemm_step(g_tBm, xs, As, acc, tid, n0, b0);

    float2 v[4][4];
#pragma unroll
    for (int j = 0; j < 4; j++)
#pragma unroll
        for (int ip = 0; ip < 4; ip++) v[j][ip] = upk(acc[j][ip]);

    store_nb(g_Bx + (size_t)t * (NDIM * BATCH), v, n0, b0);
}

__global__ __launch_bounds__(256) void k_chunk(
    const float* __restrict__ Einit, float* __restrict__ out,
    float* __restrict__ Sout, float* __restrict__ hfinal, int pass)
{
    float* As = smem;
    float* hbuf0 = smem + 32 * NDIM;
    float* hbuf1 = hbuf0 + NDIM * BATCH;
    const int tid = threadIdx.x;
    const int c = blockIdx.x;
    const int b0 = (tid & 3) * 4, n0 = (tid >> 2) * 8;

    if (pass == 2 && c > 0) {
        const float4* src = (const float4*)(Einit + (size_t)(c - 1) * (NDIM * BATCH));
        for (int i = tid; i < NDIM * BATCH / 4; i += 256) ((float4*)hbuf0)[i] = src[i];
    } else {
        float4 z = make_float4(0.f, 0.f, 0.f, 0.f);
        for (int i = tid; i < NDIM * BATCH / 4; i += 256) ((float4*)hbuf0)[i] = z;
    }
    __syncthreads();

    int cur = 0;
#pragma unroll 1
    for (int s = 0; s < CLEN; s++) {
        const int t = c * CLEN + s;
        float* hc = cur ? hbuf1 : hbuf0;
        float* hn = cur ? hbuf0 : hbuf1;

        u64 acc[4][4];
        gemm_step(g_tA, hc, As, acc, tid, n0, b0);

        float2 v[4][4];
#pragma unroll
        for (int j = 0; j < 4; j++)
#pragma unroll
            for (int ip = 0; ip < 4; ip++) v[j][ip] = upk(acc[j][ip]);

        add_nb(g_Bx + (size_t)t * (NDIM * BATCH), v, n0, b0);
        store_nb(hn, v, n0, b0);

        if (pass == 2) {
#pragma unroll
            for (int j = 0; j < 4; j++) {
                float4 w0 = make_float4(v[j][0].x, v[j][0].y, v[j][1].x, v[j][1].y);
                float4 w1 = make_float4(v[j][2].x, v[j][2].y, v[j][3].x, v[j][3].y);
                float* orow = out + (size_t)(b0 + j) * ((size_t)L_SEQ * NDIM)
                                  + (size_t)t * NDIM + n0;
                *(float4*)orow = w0;
                *(float4*)(orow + 4) = w1;
            }
        }
        __syncthreads();
        cur ^= 1;
    }

    float* hf = cur ? hbuf1 : hbuf0;
    if (pass == 1) {
        float4* dst = (float4*)(Sout + (size_t)c * (NDIM * BATCH));
        for (int i = tid; i < NDIM * BATCH / 4; i += 256) dst[i] = ((float4*)hf)[i];
    }
    if (pass == 2 && c == NCH - 1 && hfinal != nullptr) {
        for (int i = tid; i < NDIM * BATCH / 4; i += 256)
            ((float4*)hfinal)[i] = ((float4*)hf)[i];
    }
}

__global__ __launch_bounds__(256) void k_scan(
    const float* __restrict__ Esrc, float* __restrict__ Edst,
    const float* __restrict__ tM, int stride)
{
    float* As = smem;
    float* hs = smem + 32 * NDIM;
    const int tid = threadIdx.x;
    const int c = blockIdx.x;

    if (c < stride) {
        const float4* s = (const float4*)(Esrc + (size_t)c * (NDIM * BATCH));
        float4* d = (float4*)(Edst + (size_t)c * (NDIM * BATCH));
        for (int i = tid; i < NDIM * BATCH / 4; i += 256) d[i] = s[i];
        return;
    }
    const int b0 = (tid & 3) * 4, n0 = (tid >> 2) * 8;

    {
        const float4* s = (const float4*)(Esrc + (size_t)(c - stride) * (NDIM * BATCH));
        for (int i = tid; i < NDIM * BATCH / 4; i += 256) ((float4*)hs)[i] = s[i];
    }
    __syncthreads();

    u64 acc[4][4];
    gemm_step(tM, hs, As, acc, tid, n0, b0);

    float2 v[4][4];
#pragma unroll
    for (int j = 0; j < 4; j++)
#pragma unroll
        for (int ip = 0; ip < 4; ip++) v[j][ip] = upk(acc[j][ip]);

    add_nb(Esrc + (size_t)c * (NDIM * BATCH), v, n0, b0);
    store_nb(Edst + (size_t)c * (NDIM * BATCH), v, n0, b0);
}

extern "C" void kernel_launch(void* const* d_in, const int* in_sizes, int n_in,
                              void* d_out, int out_size)
{
    const float* inputs = (const float*)d_in[0];
    const float* A      = (const float*)d_in[1];
    const float* Bmat   = (const float*)d_in[2];
    float* out = (float*)d_out;

    float *tA, *tBm, *pw, *t0, *t1, *E;
    cudaGetSymbolAddress((void**)&tA,  g_tA);
    cudaGetSymbolAddress((void**)&tBm, g_tBm);
    cudaGetSymbolAddress((void**)&pw,  g_pw);
    cudaGetSymbolAddress((void**)&t0,  g_t0);
    cudaGetSymbolAddress((void**)&t1,  g_t1);
    cudaGetSymbolAddress((void**)&E,   g_E);
    float* E0 = E;
    float* E1 = E + (size_t)NCH * NDIM * BATCH;

    const int MAT = NDIM * NDIM;
    const int SMEM = (32 * NDIM + 2 * NDIM * BATCH) * 4;  // 128 KB
    cudaFuncSetAttribute(k_chunk, cudaFuncAttributeMaxDynamicSharedMemorySize, SMEM);
    cudaFuncSetAttribute(k_scan,  cudaFuncAttributeMaxDynamicSharedMemorySize, SMEM);
    cudaFuncSetAttribute(k_bx,    cudaFuncAttributeMaxDynamicSharedMemorySize, SMEM);

    k_tr<<<dim3(16, 16), dim3(32, 8)>>>(A, tA);
    k_tr<<<dim3(16, 16), dim3(32, 8)>>>(Bmat, tBm);

    k_bx<<<L_SEQ, 256, SMEM>>>(inputs);

    // powers: tA^2 -> t0, ^4 -> t1, ^8 -> t0, ^16 -> pw[0], pw[j+1] = pw[j]^2
    k_sq<<<dim3(8, 8), 256>>>(tA, t0);
    k_sq<<<dim3(8, 8), 256>>>(t0, t1);
    k_sq<<<dim3(8, 8), 256>>>(t1, t0);
    k_sq<<<dim3(8, 8), 256>>>(t0, pw);
    for (int j = 0; j < 6; j++)
        k_sq<<<dim3(8, 8), 256>>>(pw + (size_t)j * MAT, pw + (size_t)(j + 1) * MAT);

    // pass 1: local chunk end states -> E0
    k_chunk<<<NCH, 256, SMEM>>>(nullptr, nullptr, E0, nullptr, 1);

    // Kogge-Stone: 7 rounds, ping-pong E0/E1 (final lands in E1)
    const float* src = E0; float* dst = E1;
    for (int j = 0; j < 7; j++) {
        k_scan<<<NCH, 256, SMEM>>>(src, dst, pw + (size_t)j * MAT, 1 << j);
        const float* tmp = dst; dst = (float*)src; src = tmp;
    }
    // after loop, final result is in `src` (last dst) = E1

    const size_t OUT_MAIN = (size_t)BATCH * L_SEQ * NDIM;
    float* hfinal = ((size_t)out_size > OUT_MAIN) ? out + OUT_MAIN : nullptr;

    // pass 2: re-run chunks from true initial states, write outputs
    k_chunk<<<NCH, 256, SMEM>>>(E1, out, nullptr, hfinal, 2);
}

// round 3
// speedup vs baseline: 1.2662x; 1.2662x over previous
#include <cuda_runtime.h>

#define L_SEQ 2048
#define BATCH 16
#define NDIM  512
#define HDIM  512
#define NCH   128
#define CLEN  16

typedef unsigned long long u64;

__device__ __align__(256) float g_tA [NDIM * NDIM];
__device__ __align__(256) float g_tBm[HDIM * NDIM];
__device__ __align__(256) float g_pw [7 * NDIM * NDIM];
__device__ __align__(256) float g_t0 [NDIM * NDIM];
__device__ __align__(256) float g_t1 [NDIM * NDIM];
__device__ __align__(256) float g_Bx [(size_t)L_SEQ * NDIM * BATCH];
__device__ __align__(256) float g_E  [2 * NCH * NDIM * BATCH];

// ---------------- f32x2 helpers ----------------
__device__ __forceinline__ u64 pk2(float x) {
    u64 r; asm("mov.b64 %0, {%1, %1};" : "=l"(r) : "f"(x)); return r;
}
__device__ __forceinline__ void fma2(u64 &d, u64 a, u64 b) {
    asm("fma.rn.f32x2 %0, %1, %2, %3;" : "=l"(d) : "l"(a), "l"(b), "l"(d));
}
__device__ __forceinline__ float2 upk(u64 v) {
    float2 f; asm("mov.b64 {%0, %1}, %2;" : "=f"(f.x), "=f"(f.y) : "l"(v)); return f;
}

// ---------------- cp.async helpers ----------------
__device__ __forceinline__ unsigned smem_u32(const void* p) {
    return (unsigned)__cvta_generic_to_shared(p);
}
__device__ __forceinline__ void cpa16(unsigned s, const float* g) {
    asm volatile("cp.async.cg.shared.global [%0], [%1], 16;" :: "r"(s), "l"(g));
}
__device__ __forceinline__ void cpa_commit() {
    asm volatile("cp.async.commit_group;");
}
template<int N> __device__ __forceinline__ void cpa_wait() {
    asm volatile("cp.async.wait_group %0;" :: "n"(N));
}

// ---------------- double-buffered GEMM core ----------------
// acc[t][b][p] += sum_k gA[k][ncol0 + n0 + 2p + {0,1}] * hs[t][k*16 + b0 + b]
// gA is k-major with row stride NDIM. MT = 64*NPT columns per CTA.
// As must hold 2 * 32 * MT floats.
template<int NPT, int TT>
__device__ __forceinline__ void gemm_db(
    const float* __restrict__ gA, int ncol0,
    const float* const (&hsarr)[TT],
    float* __restrict__ As,
    u64 (&acc)[TT][4][NPT / 2], int tid)
{
    constexpr int MT  = 64 * NPT;
    constexpr int NP  = NPT / 2;
    constexpr int OPT = (32 * MT) / (256 * 4);   // float4 cp.async ops per thread
    const int n0 = (tid >> 2) * NPT;
    const int b0 = (tid & 3) * 4;

#pragma unroll
    for (int t = 0; t < TT; t++)
#pragma unroll
        for (int j = 0; j < 4; j++)
#pragma unroll
            for (int p = 0; p < NP; p++) acc[t][j][p] = 0ull;

    auto stage = [&](int buf, int kt) {
        const float* src = gA + (size_t)kt * 32 * NDIM + ncol0;
        float* dstb = As + buf * 32 * MT;
#pragma unroll
        for (int i = 0; i < OPT; i++) {
            int idx = tid + 256 * i;
            int row = idx / (MT / 4), c4 = idx % (MT / 4);
            cpa16(smem_u32(dstb + row * MT + c4 * 4), src + (size_t)row * NDIM + c4 * 4);
        }
        cpa_commit();
    };

    stage(0, 0);

#pragma unroll 1
    for (int kt = 0; kt < 16; kt++) {
        const int cur = kt & 1;
        if (kt < 15) { stage(1 - cur, kt + 1); cpa_wait<1>(); }
        else         { cpa_wait<0>(); }
        __syncthreads();
        const float* Ac = As + cur * 32 * MT;
#pragma unroll
        for (int kk = 0; kk < 32; kk++) {
            const int k = kt * 32 + kk;
            u64 a[NP];
#pragma unroll
            for (int p = 0; p < NP; p++)
                a[p] = *(const u64*)(Ac + kk * MT + n0 + 2 * p);
#pragma unroll
            for (int t = 0; t < TT; t++) {
                float4 hb = *(const float4*)(hsarr[t] + k * BATCH + b0);
                u64 hp;
                hp = pk2(hb.x);
#pragma unroll
                for (int p = 0; p < NP; p++) fma2(acc[t][0][p], a[p], hp);
                hp = pk2(hb.y);
#pragma unroll
                for (int p = 0; p < NP; p++) fma2(acc[t][1][p], a[p], hp);
                hp = pk2(hb.z);
#pragma unroll
                for (int p = 0; p < NP; p++) fma2(acc[t][2][p], a[p], hp);
                hp = pk2(hb.w);
#pragma unroll
                for (int p = 0; p < NP; p++) fma2(acc[t][3][p], a[p], hp);
            }
        }
        __syncthreads();
    }
}

template<int NPT>
__device__ __forceinline__ void unpack_acc(u64 (&a)[4][NPT / 2], float2 (&v)[4][NPT / 2]) {
#pragma unroll
    for (int j = 0; j < 4; j++)
#pragma unroll
        for (int ip = 0; ip < NPT / 2; ip++) v[j][ip] = upk(a[j][ip]);
}

template<int NPT>
__device__ __forceinline__ void store_nb(float* dst, float2 (&v)[4][NPT / 2], int n0, int b0) {
#pragma unroll
    for (int r = 0; r < NPT; r++) {
        int ip = r >> 1;
        float4 w = (r & 1) == 0
            ? make_float4(v[0][ip].x, v[1][ip].x, v[2][ip].x, v[3][ip].x)
            : make_float4(v[0][ip].y, v[1][ip].y, v[2][ip].y, v[3][ip].y);
        *(float4*)(dst + (n0 + r) * BATCH + b0) = w;
    }
}

template<int NPT>
__device__ __forceinline__ void add_nb(const float* src, float2 (&v)[4][NPT / 2], int n0, int b0) {
#pragma unroll
    for (int r = 0; r < NPT; r++) {
        float4 q = *(const float4*)(src + (n0 + r) * BATCH + b0);
        int ip = r >> 1;
        if ((r & 1) == 0) {
            v[0][ip].x += q.x; v[1][ip].x += q.y; v[2][ip].x += q.z; v[3][ip].x += q.w;
        } else {
            v[0][ip].y += q.x; v[1][ip].y += q.y; v[2][ip].y += q.z; v[3][ip].y += q.w;
        }
    }
}

// ---------------- transpose 512x512 ----------------
__global__ void k_tr(const float* __restrict__ src, float* __restrict__ dst)
{
    __shared__ float tile[32][33];
    int x = blockIdx.x * 32 + threadIdx.x;
    int y = blockIdx.y * 32 + threadIdx.y;
#pragma unroll
    for (int r = 0; r < 32; r += 8)
        tile[threadIdx.y + r][threadIdx.x] = src[(size_t)(y + r) * NDIM + x];
    __syncthreads();
    x = blockIdx.y * 32 + threadIdx.x;
    y = blockIdx.x * 32 + threadIdx.y;
#pragma unroll
    for (int r = 0; r < 32; r += 8)
        dst[(size_t)(y + r) * NDIM + x] = tile[threadIdx.x][threadIdx.y + r];
}

// ---------------- S = P @ P (row-major 512^3), double-buffered ----------------
__global__ __launch_bounds__(256) void k_sq(
    const float* __restrict__ P, float* __restrict__ S)
{
    __shared__ float Ta[2][16][68];
    __shared__ float Tb[2][16][64];
    const int tid = threadIdx.x;
    const int ib = blockIdx.y * 64, jb = blockIdx.x * 64;
    const int i0 = (tid >> 4) * 4, j0 = (tid & 15) * 4;
    const int ia = tid >> 2,  k4 = (tid & 3) * 4;
    const int kb = tid >> 4,  j4 = (tid & 15) * 4;
    u64 acc[4][2];
#pragma unroll
    for (int i = 0; i < 4; i++) { acc[i][0] = 0ull; acc[i][1] = 0ull; }

    float4 qa = *(const float4*)(P + (size_t)(ib + ia) * NDIM + k4);
    float4 qb = *(const float4*)(P + (size_t)kb * NDIM + jb + j4);
    Ta[0][k4 + 0][ia] = qa.x; Ta[0][k4 + 1][ia] = qa.y;
    Ta[0][k4 + 2][ia] = qa.z; Ta[0][k4 + 3][ia] = qa.w;
    *(float4*)&Tb[0][kb][j4] = qb;
    __syncthreads();

#pragma unroll 1
    for (int kt = 0; kt < 32; kt++) {
        const int cur = kt & 1;
        if (kt < 31) {
            const int k0n = (kt + 1) * 16;
            qa = *(const float4*)(P + (size_t)(ib + ia) * NDIM + k0n + k4);
            qb = *(const float4*)(P + (size_t)(k0n + kb) * NDIM + jb + j4);
        }
#pragma unroll
        for (int k = 0; k < 16; k++) {
            float4 av = *(const float4*)&Ta[cur][k][i0];
            ulonglong2 bv = *(const ulonglong2*)&Tb[cur][k][j0];
            u64 ap;
            ap = pk2(av.x); fma2(acc[0][0], bv.x, ap); fma2(acc[0][1], bv.y, ap);
            ap = pk2(av.y); fma2(acc[1][0], bv.x, ap); fma2(acc[1][1], bv.y, ap);
            ap = pk2(av.z); fma2(acc[2][0], bv.x, ap); fma2(acc[2][1], bv.y, ap);
            ap = pk2(av.w); fma2(acc[3][0], bv.x, ap); fma2(acc[3][1], bv.y, ap);
        }
        if (kt < 31) {
            const int nb = 1 - cur;
            Ta[nb][k4 + 0][ia] = qa.x; Ta[nb][k4 + 1][ia] = qa.y;
            Ta[nb][k4 + 2][ia] = qa.z; Ta[nb][k4 + 3][ia] = qa.w;
            *(float4*)&Tb[nb][kb][j4] = qb;
        }
        __syncthreads();
    }
#pragma unroll
    for (int i = 0; i < 4; i++) {
        float2 p0 = upk(acc[i][0]), p1 = upk(acc[i][1]);
        float4 w = make_float4(p0.x, p0.y, p1.x, p1.y);
        *(float4*)(S + (size_t)(ib + i0 + i) * NDIM + jb + j0) = w;
    }
}

extern __shared__ float smem[];

// ---------------- Bx projection: 2 timesteps per CTA ----------------
__global__ __launch_bounds__(256) void k_bx(const float* __restrict__ inputs)
{
    float* As  = smem;                 // 2*32*512 = 32768 floats
    float* xs0 = smem + 32768;
    float* xs1 = xs0 + NDIM * BATCH;
    const int tid = threadIdx.x;
    const int t0 = blockIdx.x * 2;
    const int n0 = (tid >> 2) * 8, b0 = (tid & 3) * 4;

    for (int i = tid; i < NDIM * BATCH; i += 256) {
        int b = i >> 9, h = i & (HDIM - 1);
        xs0[h * BATCH + b] = inputs[(size_t)b * (L_SEQ * HDIM) + (size_t)t0 * HDIM + h];
        xs1[h * BATCH + b] = inputs[(size_t)b * (L_SEQ * HDIM) + (size_t)(t0 + 1) * HDIM + h];
    }
    // gemm_db's internal first __syncthreads orders xs visibility

    u64 acc[2][4][4];
    const float* hsa[2] = { xs0, xs1 };
    gemm_db<8, 2>(g_tBm, 0, hsa, As, acc, tid);

#pragma unroll
    for (int t = 0; t < 2; t++) {
        float2 v[4][4];
        unpack_acc<8>(acc[t], v);
        store_nb<8>(g_Bx + (size_t)(t0 + t) * (NDIM * BATCH), v, n0, b0);
    }
}

// ---------------- chunk recurrence (pass 1 / pass 2) ----------------
__global__ __launch_bounds__(256) void k_chunk(
    const float* __restrict__ Einit, float* __restrict__ out,
    float* __restrict__ Sout, float* __restrict__ hfinal, int pass)
{
    float* As = smem;                      // 32768 floats
    float* hbuf0 = smem + 32768;
    float* hbuf1 = hbuf0 + NDIM * BATCH;
    const int tid = threadIdx.x;
    const int c = blockIdx.x;
    const int n0 = (tid >> 2) * 8, b0 = (tid & 3) * 4;

    if (pass == 2 && c > 0) {
        const float4* src = (const float4*)(Einit + (size_t)(c - 1) * (NDIM * BATCH));
        for (int i = tid; i < NDIM * BATCH / 4; i += 256) ((float4*)hbuf0)[i] = src[i];
    } else {
        float4 z = make_float4(0.f, 0.f, 0.f, 0.f);
        for (int i = tid; i < NDIM * BATCH / 4; i += 256) ((float4*)hbuf0)[i] = z;
    }
    __syncthreads();

    int cur = 0;
#pragma unroll 1
    for (int s = 0; s < CLEN; s++) {
        const int t = c * CLEN + s;
        float* hc = cur ? hbuf1 : hbuf0;
        float* hn = cur ? hbuf0 : hbuf1;

        // prefetch Bx[t] into registers (hidden under the GEMM)
        float4 bxr[8];
        const float* bx = g_Bx + (size_t)t * (NDIM * BATCH);
#pragma unroll
        for (int r = 0; r < 8; r++)
            bxr[r] = *(const float4*)(bx + (n0 + r) * BATCH + b0);

        u64 acc[1][4][4];
        const float* hsa[1] = { hc };
        gemm_db<8, 1>(g_tA, 0, hsa, As, acc, tid);

        float2 v[4][4];
        unpack_acc<8>(acc[0], v);
#pragma unroll
        for (int r = 0; r < 8; r++) {
            int ip = r >> 1;
            if ((r & 1) == 0) {
                v[0][ip].x += bxr[r].x; v[1][ip].x += bxr[r].y;
                v[2][ip].x += bxr[r].z; v[3][ip].x += bxr[r].w;
            } else {
                v[0][ip].y += bxr[r].x; v[1][ip].y += bxr[r].y;
                v[2][ip].y += bxr[r].z; v[3][ip].y += bxr[r].w;
            }
        }
        store_nb<8>(hn, v, n0, b0);

        if (pass == 2) {
#pragma unroll
            for (int j = 0; j < 4; j++) {
                float4 w0 = make_float4(v[j][0].x, v[j][0].y, v[j][1].x, v[j][1].y);
                float4 w1 = make_float4(v[j][2].x, v[j][2].y, v[j][3].x, v[j][3].y);
                float* orow = out + (size_t)(b0 + j) * ((size_t)L_SEQ * NDIM)
                                  + (size_t)t * NDIM + n0;
                *(float4*)orow = w0;
                *(float4*)(orow + 4) = w1;
            }
        }
        __syncthreads();
        cur ^= 1;
    }

    float* hf = cur ? hbuf1 : hbuf0;
    if (pass == 1) {
        float4* dst = (float4*)(Sout + (size_t)c * (NDIM * BATCH));
        for (int i = tid; i < NDIM * BATCH / 4; i += 256) dst[i] = ((float4*)hf)[i];
    }
    if (pass == 2 && c == NCH - 1 && hfinal != nullptr) {
        for (int i = tid; i < NDIM * BATCH / 4; i += 256)
            ((float4*)hfinal)[i] = ((float4*)hf)[i];
    }
}

// ---------------- Kogge-Stone round, 4-way M split ----------------
__global__ __launch_bounds__(256) void k_scan(
    const float* __restrict__ Esrc, float* __restrict__ Edst,
    const float* __restrict__ tM, int stride)
{
    float* As = smem;                  // 2*32*128 = 8192 floats
    float* hs = smem + 8192;           // 8192 floats
    const int tid = threadIdx.x;
    const int c = blockIdx.x;
    const int q = blockIdx.y;
    const size_t base = (size_t)c * (NDIM * BATCH);

    if (c < stride) {   // identity prefix: copy through (quarter per q)
        const float4* s = (const float4*)(Esrc + base) + q * 512;
        float4* d = (float4*)(Edst + base) + q * 512;
        for (int i = tid; i < 512; i += 256) d[i] = s[i];
        return;
    }

    {   // stage hs = Esrc[c - stride]
        const float4* s = (const float4*)(Esrc + base - (size_t)stride * (NDIM * BATCH));
        for (int i = tid; i < NDIM * BATCH / 4; i += 256) ((float4*)hs)[i] = s[i];
    }

    const int n0 = (tid >> 2) * 2, b0 = (tid & 3) * 4;
    u64 acc[1][4][1];
    const float* hsa[1] = { hs };
    gemm_db<2, 1>(tM, q * 128, hsa, As, acc, tid);

    float2 v[4][1];
    unpack_acc<2>(acc[0], v);

    const float* addp = Esrc + base + (size_t)q * 128 * BATCH;
    float* dstp = Edst + base + (size_t)q * 128 * BATCH;
    add_nb<2>(addp, v, n0, b0);
    store_nb<2>(dstp, v, n0, b0);
}

// ---------------- host launcher ----------------
extern "C" void kernel_launch(void* const* d_in, const int* in_sizes, int n_in,
                              void* d_out, int out_size)
{
    const float* inputs = (const float*)d_in[0];
    const float* A      = (const float*)d_in[1];
    const float* Bmat   = (const float*)d_in[2];
    float* out = (float*)d_out;

    float *tA, *tBm, *pw, *t0, *t1, *E;
    cudaGetSymbolAddress((void**)&tA,  g_tA);
    cudaGetSymbolAddress((void**)&tBm, g_tBm);
    cudaGetSymbolAddress((void**)&pw,  g_pw);
    cudaGetSymbolAddress((void**)&t0,  g_t0);
    cudaGetSymbolAddress((void**)&t1,  g_t1);
    cudaGetSymbolAddress((void**)&E,   g_E);
    float* E0 = E;
    float* E1 = E + (size_t)NCH * NDIM * BATCH;

    const int MAT = NDIM * NDIM;
    const int SMEM_BIG  = (2 * 32 * NDIM + 2 * NDIM * BATCH) * 4;  // 192 KB
    const int SMEM_SCAN = (2 * 32 * 128 + NDIM * BATCH) * 4;       // 64 KB
    cudaFuncSetAttribute(k_chunk, cudaFuncAttributeMaxDynamicSharedMemorySize, SMEM_BIG);
    cudaFuncSetAttribute(k_bx,    cudaFuncAttributeMaxDynamicSharedMemorySize, SMEM_BIG);
    cudaFuncSetAttribute(k_scan,  cudaFuncAttributeMaxDynamicSharedMemorySize, SMEM_SCAN);

    k_tr<<<dim3(16, 16), dim3(32, 8)>>>(A, tA);
    k_tr<<<dim3(16, 16), dim3(32, 8)>>>(Bmat, tBm);

    k_bx<<<L_SEQ / 2, 256, SMEM_BIG>>>(inputs);

    // powers: tA^2 -> t0, ^4 -> t1, ^8 -> t0, ^16 -> pw[0], pw[j+1] = pw[j]^2
    k_sq<<<dim3(8, 8), 256>>>(tA, t0);
    k_sq<<<dim3(8, 8), 256>>>(t0, t1);
    k_sq<<<dim3(8, 8), 256>>>(t1, t0);
    k_sq<<<dim3(8, 8), 256>>>(t0, pw);
    for (int j = 0; j < 6; j++)
        k_sq<<<dim3(8, 8), 256>>>(pw + (size_t)j * MAT, pw + (size_t)(j + 1) * MAT);

    // pass 1: local chunk end states -> E0
    k_chunk<<<NCH, 256, SMEM_BIG>>>(nullptr, nullptr, E0, nullptr, 1);

    // Kogge-Stone: 7 rounds, ping-pong E0/E1 (final lands in E1)
    const float* src = E0; float* dst = E1;
    for (int j = 0; j < 7; j++) {
        k_scan<<<dim3(NCH, 4), 256, SMEM_SCAN>>>(src, dst, pw + (size_t)j * MAT, 1 << j);
        const float* tmp = dst; dst = (float*)src; src = tmp;
    }

    const size_t OUT_MAIN = (size_t)BATCH * L_SEQ * NDIM;
    float* hfinal = ((size_t)out_size > OUT_MAIN) ? out + OUT_MAIN : nullptr;

    // pass 2: re-run chunks from true initial states, write outputs
    k_chunk<<<NCH, 256, SMEM_BIG>>>(E1, out, nullptr, hfinal, 2);
}